// round 14
// baseline (speedup 1.0000x reference)
#include <cuda_runtime.h>
#include <cuda_bf16.h>
#include <math.h>
#include <stdint.h>

#define NB   2
#define TT   2048
#define DD   1024
#define HH   16
#define HDD  64
#define WL   127
#define WR   128

#define SRB  144   // attn smem row stride (bytes)
#define APLB 9216  // attn K/V plane bytes: 64 rows * SRB
#define QPL  18432 // attn Q plane bytes: 128 rows * SRB
#define KVSTG (4 * APLB)            // 36864 per K/V stage
#define ASMEM (2 * QPL + 2 * KVSTG) // 110592 attn smem

// GEMM staging (BK=32): 64B data + 16B pad per row
#define GSRB 80
#define GPLB (128 * GSRB)    // 10240
#define GBUF (4 * GPLB)      // 40960 bytes per stage (4 planes)
#define GSMEM (2 * GBUF)     // 81920 (also holds 128x132 fp32 epilogue tile)

// Scratch (allocation-free)
__device__ uint16_t g_ahi[(size_t)NB * TT * DD];
__device__ uint16_t g_alo[(size_t)NB * TT * DD];
__device__ uint16_t g_bhi[(size_t)3 * DD * DD];
__device__ uint16_t g_blo[(size_t)3 * DD * DD];
#define APL ((size_t)NB * HH * TT * HDD)
__device__ uint16_t g_qh[APL], g_ql[APL];
__device__ uint16_t g_kh[APL], g_kl[APL];
__device__ uint16_t g_vth[APL], g_vtl[APL];

// ---------------------------------------------------------------------------
__device__ __forceinline__ uint32_t smem_u32(const void* p) {
    uint32_t r;
    asm("{ .reg .u64 t; cvta.to.shared.u64 t, %1; cvt.u32.u64 %0, t; }"
        : "=r"(r) : "l"(p));
    return r;
}
__device__ __forceinline__ void cp_async16(uint32_t s, const void* g) {
    asm volatile("cp.async.cg.shared.global [%0], [%1], 16;" :: "r"(s), "l"(g));
}
__device__ __forceinline__ void cp_commit() {
    asm volatile("cp.async.commit_group;" ::: "memory");
}
template <int N_> __device__ __forceinline__ void cp_wait() {
    asm volatile("cp.async.wait_group %0;" :: "n"(N_) : "memory");
}
__device__ __forceinline__ void ldsm_x4(uint32_t* r, uint32_t addr) {
    asm volatile("ldmatrix.sync.aligned.m8n8.x4.shared.b16 {%0,%1,%2,%3}, [%4];"
                 : "=r"(r[0]), "=r"(r[1]), "=r"(r[2]), "=r"(r[3]) : "r"(addr));
}
__device__ __forceinline__ uint16_t f2bf(float x) {
    return __bfloat16_as_ushort(__float2bfloat16_rn(x));
}
__device__ __forceinline__ uint32_t pack_hi_lo(float a, float b, uint32_t& lo) {
    uint16_t ha = f2bf(a), hb = f2bf(b);
    float ra = a - __uint_as_float((uint32_t)ha << 16);
    float rb = b - __uint_as_float((uint32_t)hb << 16);
    lo = (uint32_t)f2bf(ra) | ((uint32_t)f2bf(rb) << 16);
    return (uint32_t)ha | ((uint32_t)hb << 16);
}

#define MMA_BF16(ACC, A, B0, B1)                                               \
    asm volatile(                                                              \
        "mma.sync.aligned.m16n8k16.row.col.f32.bf16.bf16.f32 "                 \
        "{%0,%1,%2,%3}, {%4,%5,%6,%7}, {%8,%9}, {%0,%1,%2,%3};"                \
        : "+f"(ACC[0]), "+f"(ACC[1]), "+f"(ACC[2]), "+f"(ACC[3])               \
        : "r"((A)[0]), "r"((A)[1]), "r"((A)[2]), "r"((A)[3]), "r"(B0), "r"(B1))

// ---------------------------------------------------------------------------
__global__ __launch_bounds__(256) void split_kernel(
    const float* __restrict__ in, uint16_t* __restrict__ hi,
    uint16_t* __restrict__ lo, int n4)
{
    int i = blockIdx.x * blockDim.x + threadIdx.x;
    if (i >= n4) return;
    float4 v = ((const float4*)in)[i];
    ushort4 h, l;
    h.x = f2bf(v.x); l.x = f2bf(v.x - __uint_as_float((uint32_t)h.x << 16));
    h.y = f2bf(v.y); l.y = f2bf(v.y - __uint_as_float((uint32_t)h.y << 16));
    h.z = f2bf(v.z); l.z = f2bf(v.z - __uint_as_float((uint32_t)h.z << 16));
    h.w = f2bf(v.w); l.w = f2bf(v.w - __uint_as_float((uint32_t)h.w << 16));
    ((ushort4*)hi)[i] = h;
    ((ushort4*)lo)[i] = l;
}

// ---------------------------------------------------------------------------
// 3-term bf16 mma GEMM, 128x128xBK32 (R13 passing version, unchanged).
// mode 0: C = A@B^T + bias.  mode 1: fused qkv epilogue (RoPE/split/vtrans).
// ---------------------------------------------------------------------------
__global__ __launch_bounds__(256) void gemm_3xbf16(
    const uint16_t* __restrict__ Ahi, const uint16_t* __restrict__ Alo,
    const uint16_t* __restrict__ Bhi, const uint16_t* __restrict__ Blo,
    const float* __restrict__ bias, float* __restrict__ C,
    int M, int N, int K, int mode)
{
    extern __shared__ char smem[];
    const int tid  = threadIdx.x;
    const int wid  = tid >> 5;
    const int lane = tid & 31;
    const int g    = lane >> 2;
    const int t    = lane & 3;
    const int warpM = (wid >> 2) * 64;
    const int warpN = (wid & 3) * 32;
    const int m0 = blockIdx.y * 128;
    const int n0 = blockIdx.x * 128;

    const uint32_t sbase = smem_u32(smem);

    const int aRow = ((lane >> 3) & 1) * 8 + (lane & 7);
    const int aKb  = (lane >> 4) * 16;
    const int bRow = ((lane >> 4) & 1) * 8 + (lane & 7);
    const int bKb  = ((lane >> 3) & 1) * 16;

    uint32_t aOffH[4], aOffL[4], bOffH[2], bOffL[2];
    #pragma unroll
    for (int mi = 0; mi < 4; mi++) {
        uint32_t off = (uint32_t)((warpM + mi * 16 + aRow) * GSRB + aKb);
        aOffH[mi] = sbase + off;
        aOffL[mi] = sbase + GPLB + off;
    }
    #pragma unroll
    for (int j = 0; j < 2; j++) {
        uint32_t off = (uint32_t)((warpN + j * 16 + bRow) * GSRB + bKb);
        bOffH[j] = sbase + 2u * GPLB + off;
        bOffL[j] = sbase + 3u * GPLB + off;
    }

    auto load_tile = [&](int kt, int b) {
        const uint32_t dst = sbase + (uint32_t)b * GBUF;
        const uint16_t* gp[4];
        gp[0] = Ahi + (size_t)m0 * K + kt * 32;
        gp[1] = Alo + (size_t)m0 * K + kt * 32;
        gp[2] = Bhi + (size_t)n0 * K + kt * 32;
        gp[3] = Blo + (size_t)n0 * K + kt * 32;
        #pragma unroll
        for (int c = 0; c < 2; c++) {
            int idx = tid + c * 256;
            int row = idx >> 2, j = idx & 3;
            uint32_t soff = (uint32_t)(row * GSRB + j * 16);
            #pragma unroll
            for (int pl = 0; pl < 4; pl++)
                cp_async16(dst + pl * (uint32_t)GPLB + soff,
                           gp[pl] + (size_t)row * K + j * 8);
        }
        cp_commit();
    };

    float acc[4][4][4];
    #pragma unroll
    for (int mi = 0; mi < 4; mi++)
        #pragma unroll
        for (int ni = 0; ni < 4; ni++)
            #pragma unroll
            for (int r = 0; r < 4; r++) acc[mi][ni][r] = 0.0f;

    const int ktiles = K / 32;
    load_tile(0, 0);

    for (int kt = 0; kt < ktiles; kt++) {
        const int buf = kt & 1;
        if (kt + 1 < ktiles) { load_tile(kt + 1, buf ^ 1); cp_wait<1>(); }
        else                 { cp_wait<0>(); }
        __syncthreads();

        const uint32_t bo = (uint32_t)buf * GBUF;

        #pragma unroll
        for (int s = 0; s < 2; s++) {
            const uint32_t so = bo + (uint32_t)s * 32u;
            uint32_t ah[4][4], al[4][4], bfh[2][4], bfl[2][4];
            #pragma unroll
            for (int mi = 0; mi < 4; mi++) ldsm_x4(ah[mi], aOffH[mi] + so);
            #pragma unroll
            for (int mi = 0; mi < 4; mi++) ldsm_x4(al[mi], aOffL[mi] + so);
            #pragma unroll
            for (int j = 0; j < 2; j++) ldsm_x4(bfh[j], bOffH[j] + so);
            #pragma unroll
            for (int j = 0; j < 2; j++) ldsm_x4(bfl[j], bOffL[j] + so);

            #pragma unroll
            for (int mi = 0; mi < 4; mi++)
                #pragma unroll
                for (int ni = 0; ni < 4; ni++) {
                    const uint32_t* Bh = &bfh[ni >> 1][(ni & 1) * 2];
                    const uint32_t* Bl = &bfl[ni >> 1][(ni & 1) * 2];
                    MMA_BF16(acc[mi][ni], al[mi], Bh[0], Bh[1]);
                    MMA_BF16(acc[mi][ni], ah[mi], Bl[0], Bl[1]);
                    MMA_BF16(acc[mi][ni], ah[mi], Bh[0], Bh[1]);
                }
        }
        __syncthreads();
    }

    if (mode == 0) {
        #pragma unroll
        for (int mi = 0; mi < 4; mi++) {
            const int row = m0 + warpM + mi * 16 + g;
            #pragma unroll
            for (int ni = 0; ni < 4; ni++) {
                const int col = n0 + warpN + ni * 8 + t * 2;
                float bx = bias ? bias[col] : 0.f;
                float by = bias ? bias[col + 1] : 0.f;
                float2 v0 = make_float2(acc[mi][ni][0] + bx, acc[mi][ni][1] + by);
                float2 v1 = make_float2(acc[mi][ni][2] + bx, acc[mi][ni][3] + by);
                *(float2*)(C + (size_t)row * N + col)       = v0;
                *(float2*)(C + (size_t)(row + 8) * N + col) = v1;
            }
        }
        return;
    }

    // ---- mode 1: fused qkv epilogue ----
    float* Cs = (float*)smem;                 // [128][132]
    #pragma unroll
    for (int mi = 0; mi < 4; mi++) {
        const int r = warpM + mi * 16 + g;
        #pragma unroll
        for (int ni = 0; ni < 4; ni++) {
            const int c = warpN + ni * 8 + t * 2;
            Cs[r * 132 + c]           = acc[mi][ni][0];
            Cs[r * 132 + c + 1]       = acc[mi][ni][1];
            Cs[(r + 8) * 132 + c]     = acc[mi][ni][2];
            Cs[(r + 8) * 132 + c + 1] = acc[mi][ni][3];
        }
    }
    __syncthreads();

    const int region = n0 >> 10;              // 0=q, 1=k, 2=v
    const int h0 = (n0 & 1023) >> 6;

    if (region < 2) {
        uint16_t* H = region ? g_kh : g_qh;
        uint16_t* L = region ? g_kl : g_ql;
        const float scale = region ? 1.0f : 0.125f;
        for (int e = tid; e < 8192; e += 256) {
            int r  = e >> 6;
            int p  = e & 63;
            int hh = p >> 5;
            int d  = p & 31;
            int m  = m0 + r;
            int tp = m & (TT - 1);
            int nb = m >> 11;
            float x1 = Cs[r * 132 + hh * 64 + d];
            float x2 = Cs[r * 132 + hh * 64 + d + 32];
            float inv = exp2f(-0.41524101186092029f * (float)d);
            float fr  = (float)tp * inv;
            float c, s;
            sincosf(fr, &s, &c);
            float y1 = (x1 * c - x2 * s) * scale;
            float y2 = (x2 * c + x1 * s) * scale;
            size_t dst = ((size_t)((nb * HH + h0 + hh) * TT) + tp) * HDD + d;
            uint16_t h1 = f2bf(y1);
            uint16_t h2 = f2bf(y2);
            H[dst]      = h1;
            H[dst + 32] = h2;
            L[dst]      = f2bf(y1 - __uint_as_float((uint32_t)h1 << 16));
            L[dst + 32] = f2bf(y2 - __uint_as_float((uint32_t)h2 << 16));
        }
    } else {
        for (int e = tid; e < 16384; e += 256) {
            int cidx = e >> 7;
            int r    = e & 127;
            int m  = m0 + r;
            int tp = m & (TT - 1);
            int nb = m >> 11;
            int hh = cidx >> 6;
            int d  = cidx & 63;
            float v = Cs[r * 132 + cidx];
            uint16_t hb = f2bf(v);
            size_t dst = ((size_t)((nb * HH + h0 + hh) * HDD) + d) * TT + tp;
            g_vth[dst] = hb;
            g_vtl[dst] = f2bf(v - __uint_as_float((uint32_t)hb << 16));
        }
    }
}

// ---------------------------------------------------------------------------
// Flash attention, 3-term bf16 mma. 128 queries/CTA, 256 threads (8 warps),
// double-buffered K/V tiles with software pipelining.
// ---------------------------------------------------------------------------
__global__ __launch_bounds__(256) void attn_mma(
    const uint16_t* __restrict__ Qh, const uint16_t* __restrict__ Ql,
    const uint16_t* __restrict__ Kh, const uint16_t* __restrict__ Kl,
    const uint16_t* __restrict__ Vh, const uint16_t* __restrict__ Vl,
    uint16_t* __restrict__ Oh, uint16_t* __restrict__ Ol)
{
    extern __shared__ char smem[];
    const uint32_t sb  = smem_u32(smem);
    const uint32_t sQh = sb, sQl = sb + QPL;
    const uint32_t kvb = sb + 2 * QPL;

    const int q0 = blockIdx.x * 128;
    const int h  = blockIdx.y;
    const int n  = blockIdx.z;
    const int tid = threadIdx.x;
    const int wid = tid >> 5;                 // 0..7, warp owns q rows wid*16..+16
    const int lane = tid & 31;
    const int g = lane >> 2;
    const int t = lane & 3;

    const size_t headoff  = (size_t)(n * HH + h) * TT * HDD;   // [t][d]
    const size_t vheadoff = (size_t)(n * HH + h) * HDD * TT;   // [d][t]

    const int aRow = ((lane >> 3) & 1) * 8 + (lane & 7);
    const int aKb  = (lane >> 4) * 16;
    const int bRow = ((lane >> 4) & 1) * 8 + (lane & 7);
    const int bKb  = ((lane >> 3) & 1) * 16;

    const int kt0 = max(0, q0 - WL) & ~63;
    const int khi = min(TT - 1, q0 + 127 + WR);
    const int nt  = (khi - kt0) / 64 + 1;

    // KV tile loader (4 planes x 64 rows x 8 chunks = 2048 chunks, 8/thread)
    auto load_kv = [&](int kt, int stg) {
        const uint32_t base = kvb + (uint32_t)stg * KVSTG;
        #pragma unroll
        for (int c = 0; c < 8; c++) {
            int idx = tid + c * 256;
            int pl  = idx >> 9;               // 0..3
            int row = (idx >> 3) & 63;
            int j   = idx & 7;
            size_t okv = headoff + (size_t)(kt + row) * HDD + j * 8;
            size_t ov  = vheadoff + (size_t)row * TT + kt + j * 8;
            const uint16_t* src =
                (pl == 0) ? Kh + okv : (pl == 1) ? Kl + okv
              : (pl == 2) ? Vh + ov  :             Vl + ov;
            cp_async16(base + (uint32_t)(pl * APLB + row * SRB + j * 16), src);
        }
        cp_commit();
    };

    // prologue: Q (group 0), T0 (group 1), T1 (group 2)
    {
        #pragma unroll
        for (int c = 0; c < 8; c++) {
            int idx = tid + c * 256;          // 0..2047
            int pl  = idx >> 10;
            int row = (idx >> 3) & 127;
            int j   = idx & 7;
            const uint16_t* src = (pl ? Ql : Qh) + headoff
                                + (size_t)(q0 + row) * HDD + j * 8;
            cp_async16((pl ? sQl : sQh) + (uint32_t)(row * SRB + j * 16), src);
        }
        cp_commit();
    }
    load_kv(kt0, 0);
    if (nt > 1) load_kv(kt0 + 64, 1); else cp_commit();

    cp_wait<2>();                             // Q resident
    __syncthreads();

    uint32_t qfh[4][4], qfl[4][4];
    #pragma unroll
    for (int s = 0; s < 4; s++) {
        uint32_t off = (uint32_t)((wid * 16 + aRow) * SRB + aKb + s * 32);
        ldsm_x4(qfh[s], sQh + off);
        ldsm_x4(qfl[s], sQl + off);
    }

    float O[8][4];
    #pragma unroll
    for (int nd = 0; nd < 8; nd++)
        #pragma unroll
        for (int c = 0; c < 4; c++) O[nd][c] = 0.0f;
    float m0 = -1e30f, m1 = -1e30f, l0 = 0.0f, l1 = 0.0f;

    const int i0 = q0 + wid * 16 + g;

    for (int it = 0; it < nt; it++) {
        const int kt = kt0 + it * 64;
        cp_wait<1>();                         // T(it) resident
        __syncthreads();

        const uint32_t bo  = kvb + (uint32_t)(it & 1) * KVSTG;
        const uint32_t sKh = bo, sKl = bo + APLB;
        const uint32_t sVh = bo + 2 * APLB, sVl = bo + 3 * APLB;

        // ---- S = Q K^T ----
        float S[8][4];
        #pragma unroll
        for (int nti = 0; nti < 8; nti++)
            #pragma unroll
            for (int c = 0; c < 4; c++) S[nti][c] = 0.0f;

        #pragma unroll
        for (int s = 0; s < 4; s++) {
            uint32_t kbh[4][4], kbl[4][4];
            #pragma unroll
            for (int j = 0; j < 4; j++) {
                uint32_t off = (uint32_t)((j * 16 + bRow) * SRB + bKb + s * 32);
                ldsm_x4(kbh[j], sKh + off);
                ldsm_x4(kbl[j], sKl + off);
            }
            #pragma unroll
            for (int nti = 0; nti < 8; nti++) {
                const uint32_t* Bh = &kbh[nti >> 1][(nti & 1) * 2];
                const uint32_t* Bl = &kbl[nti >> 1][(nti & 1) * 2];
                MMA_BF16(S[nti], qfl[s], Bh[0], Bh[1]);
                MMA_BF16(S[nti], qfh[s], Bl[0], Bl[1]);
                MMA_BF16(S[nti], qfh[s], Bh[0], Bh[1]);
            }
        }

        // ---- band mask (tiles kt==q0 or kt==q0+64 are provably full-band) ----
        if (kt < q0 || kt > q0 + 64) {
            #pragma unroll
            for (int nti = 0; nti < 8; nti++)
                #pragma unroll
                for (int c = 0; c < 4; c++) {
                    int j = kt + nti * 8 + 2 * t + (c & 1);
                    int i = i0 + ((c >> 1) << 3);
                    if (j < i - WL || j > i + WR) S[nti][c] = -1e30f;
                }
        }

        // ---- online softmax ----
        float mx0 = -1e30f, mx1 = -1e30f;
        #pragma unroll
        for (int nti = 0; nti < 8; nti++) {
            mx0 = fmaxf(mx0, fmaxf(S[nti][0], S[nti][1]));
            mx1 = fmaxf(mx1, fmaxf(S[nti][2], S[nti][3]));
        }
        mx0 = fmaxf(mx0, __shfl_xor_sync(0xffffffffu, mx0, 1));
        mx0 = fmaxf(mx0, __shfl_xor_sync(0xffffffffu, mx0, 2));
        mx1 = fmaxf(mx1, __shfl_xor_sync(0xffffffffu, mx1, 1));
        mx1 = fmaxf(mx1, __shfl_xor_sync(0xffffffffu, mx1, 2));

        float mn0 = fmaxf(m0, mx0), mn1 = fmaxf(m1, mx1);
        float cr0 = __expf(m0 - mn0), cr1 = __expf(m1 - mn1);
        float mc0 = fmaxf(mn0, -1e29f), mc1 = fmaxf(mn1, -1e29f);

        float sum0 = 0.0f, sum1 = 0.0f;
        #pragma unroll
        for (int nti = 0; nti < 8; nti++) {
            S[nti][0] = __expf(S[nti][0] - mc0);
            S[nti][1] = __expf(S[nti][1] - mc0);
            S[nti][2] = __expf(S[nti][2] - mc1);
            S[nti][3] = __expf(S[nti][3] - mc1);
            sum0 += S[nti][0] + S[nti][1];
            sum1 += S[nti][2] + S[nti][3];
        }
        sum0 += __shfl_xor_sync(0xffffffffu, sum0, 1);
        sum0 += __shfl_xor_sync(0xffffffffu, sum0, 2);
        sum1 += __shfl_xor_sync(0xffffffffu, sum1, 1);
        sum1 += __shfl_xor_sync(0xffffffffu, sum1, 2);
        l0 = l0 * cr0 + sum0;
        l1 = l1 * cr1 + sum1;
        m0 = mn0; m1 = mn1;

        #pragma unroll
        for (int nd = 0; nd < 8; nd++) {
            O[nd][0] *= cr0; O[nd][1] *= cr0;
            O[nd][2] *= cr1; O[nd][3] *= cr1;
        }

        // ---- O += P V ----
        #pragma unroll
        for (int s2 = 0; s2 < 4; s2++) {
            uint32_t pah[4], pal[4];
            pah[0] = pack_hi_lo(S[2 * s2][0],     S[2 * s2][1],     pal[0]);
            pah[1] = pack_hi_lo(S[2 * s2][2],     S[2 * s2][3],     pal[1]);
            pah[2] = pack_hi_lo(S[2 * s2 + 1][0], S[2 * s2 + 1][1], pal[2]);
            pah[3] = pack_hi_lo(S[2 * s2 + 1][2], S[2 * s2 + 1][3], pal[3]);

            uint32_t vbh[4][4], vbl[4][4];
            #pragma unroll
            for (int j = 0; j < 4; j++) {
                uint32_t off = (uint32_t)((j * 16 + bRow) * SRB + bKb + s2 * 32);
                ldsm_x4(vbh[j], sVh + off);
                ldsm_x4(vbl[j], sVl + off);
            }
            #pragma unroll
            for (int nd = 0; nd < 8; nd++) {
                const uint32_t* Bh = &vbh[nd >> 1][(nd & 1) * 2];
                const uint32_t* Bl = &vbl[nd >> 1][(nd & 1) * 2];
                MMA_BF16(O[nd], pal, Bh[0], Bh[1]);
                MMA_BF16(O[nd], pah, Bl[0], Bl[1]);
                MMA_BF16(O[nd], pah, Bh[0], Bh[1]);
            }
        }
        __syncthreads();                      // all warps done with stage it&1
        if (it + 2 < nt) load_kv(kt0 + (it + 2) * 64, it & 1);
        else             cp_commit();         // keep group ledger uniform
    }

    // ---- epilogue: O/l -> bf16 hi/lo planes ----
    const float inv0 = 1.0f / l0, inv1 = 1.0f / l1;
    const int r0 = i0, r1 = i0 + 8;
    #pragma unroll
    for (int nd = 0; nd < 8; nd++) {
        const int col = h * HDD + nd * 8 + 2 * t;
        uint32_t lo0, lo1;
        uint32_t hi0 = pack_hi_lo(O[nd][0] * inv0, O[nd][1] * inv0, lo0);
        uint32_t hi1 = pack_hi_lo(O[nd][2] * inv1, O[nd][3] * inv1, lo1);
        *(uint32_t*)(Oh + (size_t)(n * TT + r0) * DD + col) = hi0;
        *(uint32_t*)(Ol + (size_t)(n * TT + r0) * DD + col) = lo0;
        *(uint32_t*)(Oh + (size_t)(n * TT + r1) * DD + col) = hi1;
        *(uint32_t*)(Ol + (size_t)(n * TT + r1) * DD + col) = lo1;
    }
}

// ---------------------------------------------------------------------------
extern "C" void kernel_launch(void* const* d_in, const int* in_sizes, int n_in,
                              void* d_out, int out_size)
{
    const float* x     = (const float*)d_in[0];
    const float* w_qkv = (const float*)d_in[1];
    const float* w_out = (const float*)d_in[2];
    const float* b_out = (const float*)d_in[3];
    float* out = (float*)d_out;

    uint16_t *ahi, *alo, *bhi, *blo, *qh, *ql, *kh, *kl, *vth, *vtl;
    cudaGetSymbolAddress((void**)&ahi, g_ahi);
    cudaGetSymbolAddress((void**)&alo, g_alo);
    cudaGetSymbolAddress((void**)&bhi, g_bhi);
    cudaGetSymbolAddress((void**)&blo, g_blo);
    cudaGetSymbolAddress((void**)&qh,  g_qh);
    cudaGetSymbolAddress((void**)&ql,  g_ql);
    cudaGetSymbolAddress((void**)&kh,  g_kh);
    cudaGetSymbolAddress((void**)&kl,  g_kl);
    cudaGetSymbolAddress((void**)&vth, g_vth);
    cudaGetSymbolAddress((void**)&vtl, g_vtl);

    const int M = NB * TT;                 // 4096

    cudaFuncSetAttribute(gemm_3xbf16, cudaFuncAttributeMaxDynamicSharedMemorySize,
                         GSMEM);
    cudaFuncSetAttribute(attn_mma, cudaFuncAttributeMaxDynamicSharedMemorySize,
                         ASMEM);

    // split x and w_qkv
    {
        int n4 = M * DD / 4;
        split_kernel<<<(n4 + 255) / 256, 256>>>(x, ahi, alo, n4);
        n4 = 3 * DD * DD / 4;
        split_kernel<<<(n4 + 255) / 256, 256>>>(w_qkv, bhi, blo, n4);
    }
    // 1) fused: qkv GEMM + RoPE + split + v-transpose -> attention planes
    {
        dim3 grid(3 * DD / 128, M / 128);
        gemm_3xbf16<<<grid, 256, GSMEM>>>(ahi, alo, bhi, blo, nullptr, nullptr,
                                          M, 3 * DD, DD, 1);
    }
    // 2) flash attention -> writes A planes for GEMM2
    {
        dim3 grid(TT / 128, HH, NB);
        attn_mma<<<grid, 256, ASMEM>>>(qh, ql, kh, kl, vth, vtl, ahi, alo);
    }
    // split w_out
    {
        int n4 = DD * DD / 4;
        split_kernel<<<(n4 + 255) / 256, 256>>>(w_out, bhi, blo, n4);
    }
    // 3) out = attn @ w_out^T + b_out
    {
        dim3 grid(DD / 128, M / 128);
        gemm_3xbf16<<<grid, 256, GSMEM>>>(ahi, alo, bhi, blo, b_out, out,
                                          M, DD, DD, 0);
    }
}

// round 16
// speedup vs baseline: 1.0701x; 1.0701x over previous
#include <cuda_runtime.h>
#include <cuda_bf16.h>
#include <math.h>
#include <stdint.h>

#define NB   2
#define TT   2048
#define DD   1024
#define HH   16
#define HDD  64
#define WL   127
#define WR   128

#define SRB  144   // attn smem row stride (bytes)
#define APLB 9216  // attn plane bytes: 64 rows * SRB
#define KVSTG (4 * APLB)   // 36864 per K/V stage
#define ASMEM (2 * KVSTG)  // 73728 attn smem (2-stage ring; Q borrows stage 1)

// GEMM staging (BK=32): 64B data + 16B pad per row
#define GSRB 80
#define GPLB (128 * GSRB)    // 10240
#define GBUF (4 * GPLB)      // 40960 bytes per stage (4 planes)
#define GSMEM (2 * GBUF)     // 81920 (also holds 128x132 fp32 epilogue tile)

// Scratch (allocation-free)
__device__ uint16_t g_ahi[(size_t)NB * TT * DD];
__device__ uint16_t g_alo[(size_t)NB * TT * DD];
__device__ uint16_t g_bhi[(size_t)3 * DD * DD];
__device__ uint16_t g_blo[(size_t)3 * DD * DD];
__device__ uint16_t g_whi[(size_t)DD * DD];
__device__ uint16_t g_wlo[(size_t)DD * DD];
#define APL ((size_t)NB * HH * TT * HDD)
__device__ uint16_t g_qh[APL], g_ql[APL];
__device__ uint16_t g_kh[APL], g_kl[APL];
__device__ uint16_t g_vth[APL], g_vtl[APL];

// ---------------------------------------------------------------------------
__device__ __forceinline__ uint32_t smem_u32(const void* p) {
    uint32_t r;
    asm("{ .reg .u64 t; cvta.to.shared.u64 t, %1; cvt.u32.u64 %0, t; }"
        : "=r"(r) : "l"(p));
    return r;
}
__device__ __forceinline__ void cp_async16(uint32_t s, const void* g) {
    asm volatile("cp.async.cg.shared.global [%0], [%1], 16;" :: "r"(s), "l"(g));
}
__device__ __forceinline__ void cp_commit() {
    asm volatile("cp.async.commit_group;" ::: "memory");
}
template <int N_> __device__ __forceinline__ void cp_wait() {
    asm volatile("cp.async.wait_group %0;" :: "n"(N_) : "memory");
}
__device__ __forceinline__ void ldsm_x4(uint32_t* r, uint32_t addr) {
    asm volatile("ldmatrix.sync.aligned.m8n8.x4.shared.b16 {%0,%1,%2,%3}, [%4];"
                 : "=r"(r[0]), "=r"(r[1]), "=r"(r[2]), "=r"(r[3]) : "r"(addr));
}
__device__ __forceinline__ uint16_t f2bf(float x) {
    return __bfloat16_as_ushort(__float2bfloat16_rn(x));
}
__device__ __forceinline__ uint32_t pack_hi_lo(float a, float b, uint32_t& lo) {
    uint16_t ha = f2bf(a), hb = f2bf(b);
    float ra = a - __uint_as_float((uint32_t)ha << 16);
    float rb = b - __uint_as_float((uint32_t)hb << 16);
    lo = (uint32_t)f2bf(ra) | ((uint32_t)f2bf(rb) << 16);
    return (uint32_t)ha | ((uint32_t)hb << 16);
}

#define MMA_BF16(ACC, A, B0, B1)                                               \
    asm volatile(                                                              \
        "mma.sync.aligned.m16n8k16.row.col.f32.bf16.bf16.f32 "                 \
        "{%0,%1,%2,%3}, {%4,%5,%6,%7}, {%8,%9}, {%0,%1,%2,%3};"                \
        : "+f"(ACC[0]), "+f"(ACC[1]), "+f"(ACC[2]), "+f"(ACC[3])               \
        : "r"((A)[0]), "r"((A)[1]), "r"((A)[2]), "r"((A)[3]), "r"(B0), "r"(B1))

// ---------------------------------------------------------------------------
// Merged split: x -> (ahi,alo), w_qkv -> (bhi,blo), w_out -> (whi,wlo).
// ---------------------------------------------------------------------------
__global__ __launch_bounds__(256) void split3_kernel(
    const float* __restrict__ x, const float* __restrict__ wqkv,
    const float* __restrict__ wout,
    uint16_t* __restrict__ ahi, uint16_t* __restrict__ alo,
    uint16_t* __restrict__ bhi, uint16_t* __restrict__ blo,
    uint16_t* __restrict__ whi, uint16_t* __restrict__ wlo)
{
    const int n4x = NB * TT * DD / 4;     // 1048576
    const int n4w = 3 * DD * DD / 4;      // 786432
    const int n4o = DD * DD / 4;          // 262144
    int i = blockIdx.x * blockDim.x + threadIdx.x;
    const float* in; uint16_t *hi, *lo; int j;
    if (i < n4x)              { in = x;    hi = ahi; lo = alo; j = i; }
    else if (i < n4x + n4w)   { in = wqkv; hi = bhi; lo = blo; j = i - n4x; }
    else if (i < n4x + n4w + n4o) { in = wout; hi = whi; lo = wlo; j = i - n4x - n4w; }
    else return;

    float4 v = ((const float4*)in)[j];
    ushort4 h, l;
    h.x = f2bf(v.x); l.x = f2bf(v.x - __uint_as_float((uint32_t)h.x << 16));
    h.y = f2bf(v.y); l.y = f2bf(v.y - __uint_as_float((uint32_t)h.y << 16));
    h.z = f2bf(v.z); l.z = f2bf(v.z - __uint_as_float((uint32_t)h.z << 16));
    h.w = f2bf(v.w); l.w = f2bf(v.w - __uint_as_float((uint32_t)h.w << 16));
    ((ushort4*)hi)[j] = h;
    ((ushort4*)lo)[j] = l;
}

// ---------------------------------------------------------------------------
// 3-term bf16 mma GEMM, 128x128xBK32 (R13 passing version, unchanged).
// mode 0: C = A@B^T + bias.  mode 1: fused qkv epilogue (RoPE/split/vtrans).
// ---------------------------------------------------------------------------
__global__ __launch_bounds__(256) void gemm_3xbf16(
    const uint16_t* __restrict__ Ahi, const uint16_t* __restrict__ Alo,
    const uint16_t* __restrict__ Bhi, const uint16_t* __restrict__ Blo,
    const float* __restrict__ bias, float* __restrict__ C,
    int M, int N, int K, int mode)
{
    extern __shared__ char smem[];
    const int tid  = threadIdx.x;
    const int wid  = tid >> 5;
    const int lane = tid & 31;
    const int g    = lane >> 2;
    const int t    = lane & 3;
    const int warpM = (wid >> 2) * 64;
    const int warpN = (wid & 3) * 32;
    const int m0 = blockIdx.y * 128;
    const int n0 = blockIdx.x * 128;

    const uint32_t sbase = smem_u32(smem);

    const int aRow = ((lane >> 3) & 1) * 8 + (lane & 7);
    const int aKb  = (lane >> 4) * 16;
    const int bRow = ((lane >> 4) & 1) * 8 + (lane & 7);
    const int bKb  = ((lane >> 3) & 1) * 16;

    uint32_t aOffH[4], aOffL[4], bOffH[2], bOffL[2];
    #pragma unroll
    for (int mi = 0; mi < 4; mi++) {
        uint32_t off = (uint32_t)((warpM + mi * 16 + aRow) * GSRB + aKb);
        aOffH[mi] = sbase + off;
        aOffL[mi] = sbase + GPLB + off;
    }
    #pragma unroll
    for (int j = 0; j < 2; j++) {
        uint32_t off = (uint32_t)((warpN + j * 16 + bRow) * GSRB + bKb);
        bOffH[j] = sbase + 2u * GPLB + off;
        bOffL[j] = sbase + 3u * GPLB + off;
    }

    auto load_tile = [&](int kt, int b) {
        const uint32_t dst = sbase + (uint32_t)b * GBUF;
        const uint16_t* gp[4];
        gp[0] = Ahi + (size_t)m0 * K + kt * 32;
        gp[1] = Alo + (size_t)m0 * K + kt * 32;
        gp[2] = Bhi + (size_t)n0 * K + kt * 32;
        gp[3] = Blo + (size_t)n0 * K + kt * 32;
        #pragma unroll
        for (int c = 0; c < 2; c++) {
            int idx = tid + c * 256;
            int row = idx >> 2, j = idx & 3;
            uint32_t soff = (uint32_t)(row * GSRB + j * 16);
            #pragma unroll
            for (int pl = 0; pl < 4; pl++)
                cp_async16(dst + pl * (uint32_t)GPLB + soff,
                           gp[pl] + (size_t)row * K + j * 8);
        }
        cp_commit();
    };

    float acc[4][4][4];
    #pragma unroll
    for (int mi = 0; mi < 4; mi++)
        #pragma unroll
        for (int ni = 0; ni < 4; ni++)
            #pragma unroll
            for (int r = 0; r < 4; r++) acc[mi][ni][r] = 0.0f;

    const int ktiles = K / 32;
    load_tile(0, 0);

    for (int kt = 0; kt < ktiles; kt++) {
        const int buf = kt & 1;
        if (kt + 1 < ktiles) { load_tile(kt + 1, buf ^ 1); cp_wait<1>(); }
        else                 { cp_wait<0>(); }
        __syncthreads();

        const uint32_t bo = (uint32_t)buf * GBUF;

        #pragma unroll
        for (int s = 0; s < 2; s++) {
            const uint32_t so = bo + (uint32_t)s * 32u;
            uint32_t ah[4][4], al[4][4], bfh[2][4], bfl[2][4];
            #pragma unroll
            for (int mi = 0; mi < 4; mi++) ldsm_x4(ah[mi], aOffH[mi] + so);
            #pragma unroll
            for (int mi = 0; mi < 4; mi++) ldsm_x4(al[mi], aOffL[mi] + so);
            #pragma unroll
            for (int j = 0; j < 2; j++) ldsm_x4(bfh[j], bOffH[j] + so);
            #pragma unroll
            for (int j = 0; j < 2; j++) ldsm_x4(bfl[j], bOffL[j] + so);

            #pragma unroll
            for (int mi = 0; mi < 4; mi++)
                #pragma unroll
                for (int ni = 0; ni < 4; ni++) {
                    const uint32_t* Bh = &bfh[ni >> 1][(ni & 1) * 2];
                    const uint32_t* Bl = &bfl[ni >> 1][(ni & 1) * 2];
                    MMA_BF16(acc[mi][ni], al[mi], Bh[0], Bh[1]);
                    MMA_BF16(acc[mi][ni], ah[mi], Bl[0], Bl[1]);
                    MMA_BF16(acc[mi][ni], ah[mi], Bh[0], Bh[1]);
                }
        }
        __syncthreads();
    }

    if (mode == 0) {
        #pragma unroll
        for (int mi = 0; mi < 4; mi++) {
            const int row = m0 + warpM + mi * 16 + g;
            #pragma unroll
            for (int ni = 0; ni < 4; ni++) {
                const int col = n0 + warpN + ni * 8 + t * 2;
                float bx = bias ? bias[col] : 0.f;
                float by = bias ? bias[col + 1] : 0.f;
                float2 v0 = make_float2(acc[mi][ni][0] + bx, acc[mi][ni][1] + by);
                float2 v1 = make_float2(acc[mi][ni][2] + bx, acc[mi][ni][3] + by);
                *(float2*)(C + (size_t)row * N + col)       = v0;
                *(float2*)(C + (size_t)(row + 8) * N + col) = v1;
            }
        }
        return;
    }

    // ---- mode 1: fused qkv epilogue ----
    float* Cs = (float*)smem;                 // [128][132]
    #pragma unroll
    for (int mi = 0; mi < 4; mi++) {
        const int r = warpM + mi * 16 + g;
        #pragma unroll
        for (int ni = 0; ni < 4; ni++) {
            const int c = warpN + ni * 8 + t * 2;
            Cs[r * 132 + c]           = acc[mi][ni][0];
            Cs[r * 132 + c + 1]       = acc[mi][ni][1];
            Cs[(r + 8) * 132 + c]     = acc[mi][ni][2];
            Cs[(r + 8) * 132 + c + 1] = acc[mi][ni][3];
        }
    }
    __syncthreads();

    const int region = n0 >> 10;              // 0=q, 1=k, 2=v
    const int h0 = (n0 & 1023) >> 6;

    if (region < 2) {
        uint16_t* H = region ? g_kh : g_qh;
        uint16_t* L = region ? g_kl : g_ql;
        const float scale = region ? 1.0f : 0.125f;
        for (int e = tid; e < 8192; e += 256) {
            int r  = e >> 6;
            int p  = e & 63;
            int hh = p >> 5;
            int d  = p & 31;
            int m  = m0 + r;
            int tp = m & (TT - 1);
            int nb = m >> 11;
            float x1 = Cs[r * 132 + hh * 64 + d];
            float x2 = Cs[r * 132 + hh * 64 + d + 32];
            float inv = exp2f(-0.41524101186092029f * (float)d);
            float fr  = (float)tp * inv;
            float c, s;
            sincosf(fr, &s, &c);
            float y1 = (x1 * c - x2 * s) * scale;
            float y2 = (x2 * c + x1 * s) * scale;
            size_t dst = ((size_t)((nb * HH + h0 + hh) * TT) + tp) * HDD + d;
            uint16_t h1 = f2bf(y1);
            uint16_t h2 = f2bf(y2);
            H[dst]      = h1;
            H[dst + 32] = h2;
            L[dst]      = f2bf(y1 - __uint_as_float((uint32_t)h1 << 16));
            L[dst + 32] = f2bf(y2 - __uint_as_float((uint32_t)h2 << 16));
        }
    } else {
        for (int e = tid; e < 16384; e += 256) {
            int cidx = e >> 7;
            int r    = e & 127;
            int m  = m0 + r;
            int tp = m & (TT - 1);
            int nb = m >> 11;
            int hh = cidx >> 6;
            int d  = cidx & 63;
            float v = Cs[r * 132 + cidx];
            uint16_t hb = f2bf(v);
            size_t dst = ((size_t)((nb * HH + h0 + hh) * HDD) + d) * TT + tp;
            g_vth[dst] = hb;
            g_vtl[dst] = f2bf(v - __uint_as_float((uint32_t)hb << 16));
        }
    }
}

// ---------------------------------------------------------------------------
// Flash attention, 3-term bf16 mma. 64 queries/CTA, 128 threads (R13 geometry)
// with 2-stage double-buffered K/V pipeline (isolated pipelining test).
// ---------------------------------------------------------------------------
__global__ __launch_bounds__(128) void attn_mma(
    const uint16_t* __restrict__ Qh, const uint16_t* __restrict__ Ql,
    const uint16_t* __restrict__ Kh, const uint16_t* __restrict__ Kl,
    const uint16_t* __restrict__ Vh, const uint16_t* __restrict__ Vl,
    uint16_t* __restrict__ Oh, uint16_t* __restrict__ Ol)
{
    extern __shared__ char smem[];
    const uint32_t sb = smem_u32(smem);

    const int q0 = blockIdx.x * 64;
    const int h  = blockIdx.y;
    const int n  = blockIdx.z;
    const int tid = threadIdx.x;
    const int wid = tid >> 5;
    const int lane = tid & 31;
    const int g = lane >> 2;
    const int t = lane & 3;

    const size_t headoff  = (size_t)(n * HH + h) * TT * HDD;
    const size_t vheadoff = (size_t)(n * HH + h) * HDD * TT;

    const int aRow = ((lane >> 3) & 1) * 8 + (lane & 7);
    const int aKb  = (lane >> 4) * 16;
    const int bRow = ((lane >> 4) & 1) * 8 + (lane & 7);
    const int bKb  = ((lane >> 3) & 1) * 16;

    const int kt0 = (max(0, q0 - WL)) & ~63;
    const int khi = min(TT - 1, q0 + 63 + WR);
    const int nt  = (khi - kt0) / 64 + 1;

    auto load_kv = [&](int kt, int stg) {
        const uint32_t base = sb + (uint32_t)stg * KVSTG;
        #pragma unroll
        for (int c = 0; c < 4; c++) {
            int idx = tid + c * 128;          // 0..511
            int row = idx >> 3, j = idx & 7;
            uint32_t soff = (uint32_t)(row * SRB + j * 16);
            cp_async16(base + soff,            Kh + headoff + (size_t)(kt + row) * HDD + j * 8);
            cp_async16(base + APLB + soff,     Kl + headoff + (size_t)(kt + row) * HDD + j * 8);
            cp_async16(base + 2 * APLB + soff, Vh + vheadoff + (size_t)row * TT + kt + j * 8);
            cp_async16(base + 3 * APLB + soff, Vl + vheadoff + (size_t)row * TT + kt + j * 8);
        }
        cp_commit();
    };

    // stage Q into stage-1 planes 0/1, then T0 into stage-0 (both in flight)
    {
        const uint32_t qb = sb + KVSTG;
        #pragma unroll
        for (int c = 0; c < 4; c++) {
            int idx = tid + c * 128;
            int row = idx >> 3, j = idx & 7;
            uint32_t soff = (uint32_t)(row * SRB + j * 16);
            cp_async16(qb + soff,        Qh + headoff + (size_t)(q0 + row) * HDD + j * 8);
            cp_async16(qb + APLB + soff, Ql + headoff + (size_t)(q0 + row) * HDD + j * 8);
        }
        cp_commit();                          // group: Q
    }
    load_kv(kt0, 0);                          // group: T0

    cp_wait<1>();                             // Q resident (T0 may be in flight)
    __syncthreads();
    uint32_t qfh[4][4], qfl[4][4];
    #pragma unroll
    for (int s = 0; s < 4; s++) {
        uint32_t off = (uint32_t)((wid * 16 + aRow) * SRB + aKb + s * 32);
        ldsm_x4(qfh[s], sb + KVSTG + off);
        ldsm_x4(qfl[s], sb + KVSTG + APLB + off);
    }
    __syncthreads();                          // Q region free for T1
    if (nt > 1) load_kv(kt0 + 64, 1); else cp_commit();   // group: T1

    float O[8][4];
    #pragma unroll
    for (int nd = 0; nd < 8; nd++)
        #pragma unroll
        for (int c = 0; c < 4; c++) O[nd][c] = 0.0f;
    float m0 = -1e30f, m1 = -1e30f, l0 = 0.0f, l1 = 0.0f;

    const int i0 = q0 + wid * 16 + g;

    for (int it = 0; it < nt; it++) {
        const int kt = kt0 + it * 64;
        cp_wait<1>();                         // T(it) resident
        __syncthreads();

        const uint32_t bo  = sb + (uint32_t)(it & 1) * KVSTG;
        const uint32_t sKh = bo, sKl = bo + APLB;
        const uint32_t sVh = bo + 2 * APLB, sVl = bo + 3 * APLB;

        float S[8][4];
        #pragma unroll
        for (int nti = 0; nti < 8; nti++)
            #pragma unroll
            for (int c = 0; c < 4; c++) S[nti][c] = 0.0f;

        #pragma unroll
        for (int s = 0; s < 4; s++) {
            uint32_t kbh[4][4], kbl[4][4];
            #pragma unroll
            for (int j = 0; j < 4; j++) {
                uint32_t off = (uint32_t)((j * 16 + bRow) * SRB + bKb + s * 32);
                ldsm_x4(kbh[j], sKh + off);
                ldsm_x4(kbl[j], sKl + off);
            }
            #pragma unroll
            for (int nti = 0; nti < 8; nti++) {
                const uint32_t* Bh = &kbh[nti >> 1][(nti & 1) * 2];
                const uint32_t* Bl = &kbl[nti >> 1][(nti & 1) * 2];
                MMA_BF16(S[nti], qfl[s], Bh[0], Bh[1]);
                MMA_BF16(S[nti], qfh[s], Bl[0], Bl[1]);
                MMA_BF16(S[nti], qfh[s], Bh[0], Bh[1]);
            }
        }

        if (kt < q0 - 64 || kt > q0 + 64) {
            #pragma unroll
            for (int nti = 0; nti < 8; nti++)
                #pragma unroll
                for (int c = 0; c < 4; c++) {
                    int j = kt + nti * 8 + 2 * t + (c & 1);
                    int i = i0 + ((c >> 1) << 3);
                    if (j < i - WL || j > i + WR) S[nti][c] = -1e30f;
                }
        }

        float mx0 = -1e30f, mx1 = -1e30f;
        #pragma unroll
        for (int nti = 0; nti < 8; nti++) {
            mx0 = fmaxf(mx0, fmaxf(S[nti][0], S[nti][1]));
            mx1 = fmaxf(mx1, fmaxf(S[nti][2], S[nti][3]));
        }
        mx0 = fmaxf(mx0, __shfl_xor_sync(0xffffffffu, mx0, 1));
        mx0 = fmaxf(mx0, __shfl_xor_sync(0xffffffffu, mx0, 2));
        mx1 = fmaxf(mx1, __shfl_xor_sync(0xffffffffu, mx1, 1));
        mx1 = fmaxf(mx1, __shfl_xor_sync(0xffffffffu, mx1, 2));

        float mn0 = fmaxf(m0, mx0), mn1 = fmaxf(m1, mx1);
        float cr0 = __expf(m0 - mn0), cr1 = __expf(m1 - mn1);
        float mc0 = fmaxf(mn0, -1e29f), mc1 = fmaxf(mn1, -1e29f);

        float sum0 = 0.0f, sum1 = 0.0f;
        #pragma unroll
        for (int nti = 0; nti < 8; nti++) {
            S[nti][0] = __expf(S[nti][0] - mc0);
            S[nti][1] = __expf(S[nti][1] - mc0);
            S[nti][2] = __expf(S[nti][2] - mc1);
            S[nti][3] = __expf(S[nti][3] - mc1);
            sum0 += S[nti][0] + S[nti][1];
            sum1 += S[nti][2] + S[nti][3];
        }
        sum0 += __shfl_xor_sync(0xffffffffu, sum0, 1);
        sum0 += __shfl_xor_sync(0xffffffffu, sum0, 2);
        sum1 += __shfl_xor_sync(0xffffffffu, sum1, 1);
        sum1 += __shfl_xor_sync(0xffffffffu, sum1, 2);
        l0 = l0 * cr0 + sum0;
        l1 = l1 * cr1 + sum1;
        m0 = mn0; m1 = mn1;

        #pragma unroll
        for (int nd = 0; nd < 8; nd++) {
            O[nd][0] *= cr0; O[nd][1] *= cr0;
            O[nd][2] *= cr1; O[nd][3] *= cr1;
        }

        #pragma unroll
        for (int s2 = 0; s2 < 4; s2++) {
            uint32_t pah[4], pal[4];
            pah[0] = pack_hi_lo(S[2 * s2][0],     S[2 * s2][1],     pal[0]);
            pah[1] = pack_hi_lo(S[2 * s2][2],     S[2 * s2][3],     pal[1]);
            pah[2] = pack_hi_lo(S[2 * s2 + 1][0], S[2 * s2 + 1][1], pal[2]);
            pah[3] = pack_hi_lo(S[2 * s2 + 1][2], S[2 * s2 + 1][3], pal[3]);

            uint32_t vbh[4][4], vbl[4][4];
            #pragma unroll
            for (int j = 0; j < 4; j++) {
                uint32_t off = (uint32_t)((j * 16 + bRow) * SRB + bKb + s2 * 32);
                ldsm_x4(vbh[j], sVh + off);
                ldsm_x4(vbl[j], sVl + off);
            }
            #pragma unroll
            for (int nd = 0; nd < 8; nd++) {
                const uint32_t* Bh = &vbh[nd >> 1][(nd & 1) * 2];
                const uint32_t* Bl = &vbl[nd >> 1][(nd & 1) * 2];
                MMA_BF16(O[nd], pal, Bh[0], Bh[1]);
                MMA_BF16(O[nd], pah, Bl[0], Bl[1]);
                MMA_BF16(O[nd], pah, Bh[0], Bh[1]);
            }
        }
        __syncthreads();                      // stage (it&1) free for prefetch
        if (it + 2 < nt) load_kv(kt0 + (it + 2) * 64, it & 1);
        else             cp_commit();         // keep group ledger uniform
    }

    const float inv0 = 1.0f / l0, inv1 = 1.0f / l1;
    const int r0 = i0, r1 = i0 + 8;
    #pragma unroll
    for (int nd = 0; nd < 8; nd++) {
        const int col = h * HDD + nd * 8 + 2 * t;
        uint32_t lo0, lo1;
        uint32_t hi0 = pack_hi_lo(O[nd][0] * inv0, O[nd][1] * inv0, lo0);
        uint32_t hi1 = pack_hi_lo(O[nd][2] * inv1, O[nd][3] * inv1, lo1);
        *(uint32_t*)(Oh + (size_t)(n * TT + r0) * DD + col) = hi0;
        *(uint32_t*)(Ol + (size_t)(n * TT + r0) * DD + col) = lo0;
        *(uint32_t*)(Oh + (size_t)(n * TT + r1) * DD + col) = hi1;
        *(uint32_t*)(Ol + (size_t)(n * TT + r1) * DD + col) = lo1;
    }
}

// ---------------------------------------------------------------------------
extern "C" void kernel_launch(void* const* d_in, const int* in_sizes, int n_in,
                              void* d_out, int out_size)
{
    const float* x     = (const float*)d_in[0];
    const float* w_qkv = (const float*)d_in[1];
    const float* w_out = (const float*)d_in[2];
    const float* b_out = (const float*)d_in[3];
    float* out = (float*)d_out;

    uint16_t *ahi, *alo, *bhi, *blo, *whi, *wlo, *qh, *ql, *kh, *kl, *vth, *vtl;
    cudaGetSymbolAddress((void**)&ahi, g_ahi);
    cudaGetSymbolAddress((void**)&alo, g_alo);
    cudaGetSymbolAddress((void**)&bhi, g_bhi);
    cudaGetSymbolAddress((void**)&blo, g_blo);
    cudaGetSymbolAddress((void**)&whi, g_whi);
    cudaGetSymbolAddress((void**)&wlo, g_wlo);
    cudaGetSymbolAddress((void**)&qh,  g_qh);
    cudaGetSymbolAddress((void**)&ql,  g_ql);
    cudaGetSymbolAddress((void**)&kh,  g_kh);
    cudaGetSymbolAddress((void**)&kl,  g_kl);
    cudaGetSymbolAddress((void**)&vth, g_vth);
    cudaGetSymbolAddress((void**)&vtl, g_vtl);

    const int M = NB * TT;                 // 4096

    cudaFuncSetAttribute(gemm_3xbf16, cudaFuncAttributeMaxDynamicSharedMemorySize,
                         GSMEM);
    cudaFuncSetAttribute(attn_mma, cudaFuncAttributeMaxDynamicSharedMemorySize,
                         ASMEM);

    // 0) all splits in one launch (x, w_qkv, w_out)
    {
        int total4 = (M * DD + 3 * DD * DD + DD * DD) / 4;   // 2097152
        split3_kernel<<<(total4 + 255) / 256, 256>>>(
            x, w_qkv, w_out, ahi, alo, bhi, blo, whi, wlo);
    }
    // 1) fused: qkv GEMM + RoPE + split + v-transpose -> attention planes
    {
        dim3 grid(3 * DD / 128, M / 128);
        gemm_3xbf16<<<grid, 256, GSMEM>>>(ahi, alo, bhi, blo, nullptr, nullptr,
                                          M, 3 * DD, DD, 1);
    }
    // 2) flash attention -> writes A planes for GEMM2
    {
        dim3 grid(TT / 64, HH, NB);
        attn_mma<<<grid, 128, ASMEM>>>(qh, ql, kh, kl, vth, vtl, ahi, alo);
    }
    // 3) out = attn @ w_out^T + b_out
    {
        dim3 grid(DD / 128, M / 128);
        gemm_3xbf16<<<grid, 256, GSMEM>>>(ahi, alo, whi, wlo, b_out, out,
                                          M, DD, DD, 0);
    }
}